// round 13
// baseline (speedup 1.0000x reference)
#include <cuda_runtime.h>

// ---------------------------------------------------------------------------
// Problem: B=8, H=126, W=126, F=64, D=32; grids padded 128x128.
// Plane-major: field[(b*32+d)][r][c]; 256 independent planes after init GEMM.
// fused_sim: 128 CTAs x 512 thr, each CTA = 2 planes -> single wave on 148 SMs.
// ---------------------------------------------------------------------------
constexpr double dDX  = 2.0 / 9.0;
constexpr double dDY  = 2.0 / 127.0;
constexpr double dDX2 = dDX * dDX;
constexpr double dDY2 = dDY * dDY;
constexpr double dDEN = 2.0 * (dDX2 + dDY2);

#define F_A    ((float)(dDY2 / dDEN))        // coeff for E/W
#define F_B    ((float)(dDX2 / dDEN))        // coeff for N/S
#define F_CB   ((float)(dDX2 * dDY2 / dDEN))
#define F_I2DX ((float)(1.0 / (2.0 * dDX)))
#define F_I2DY ((float)(1.0 / (2.0 * dDY)))
#define F_IDT  (10.0f)
#define F_DTDX ((float)(0.1 / dDX))
#define F_DTDY ((float)(0.1 / dDY))
#define F_PGX  ((float)(0.1 / (2.0 * dDX)))
#define F_PGY  ((float)(0.1 / (2.0 * dDY)))
#define F_NUX  ((float)(0.01 / dDX2))
#define F_NUY  ((float)(0.01 / dDY2))
#define F_FDT  (0.1f)

#define NPLANE_F  (128 * 128)
#define NPF4      (NPLANE_F / 4)     // 4096 float4 per plane
#define NTOT_F    (256 * NPLANE_F)

__device__ float g_pT[NTOT_F];
__device__ float g_uT[NTOT_F];
__device__ float g_vT[NTOT_F];
__device__ float g_uA[NTOT_F];
__device__ float g_vA[NTOT_F];
__device__ float g_uB[NTOT_F];
__device__ float g_vB[NTOT_F];

// ---------------------------------------------------------------------------
// Packed f32x2 helpers (init GEMM)
// ---------------------------------------------------------------------------
typedef unsigned long long ull;
__device__ __forceinline__ ull pk2(float lo, float hi) {
    ull r;
    asm("mov.b64 %0, {%1, %2};" : "=l"(r) : "f"(lo), "f"(hi));
    return r;
}
__device__ __forceinline__ void fma2(ull& acc, ull a, ull b) {
    asm("fma.rn.f32x2 %0, %1, %2, %0;" : "+l"(acc) : "l"(a), "l"(b));
}
__device__ __forceinline__ float lo32(ull v) { return __uint_as_float((unsigned)v); }
__device__ __forceinline__ float hi32(ull v) { return __uint_as_float((unsigned)(v >> 32)); }

// ---------------------------------------------------------------------------
// init_p: p[(b,d)][r][c] = sum_f xpad[b,r,c,f]*w[d,f] + b_lin[d]
// ---------------------------------------------------------------------------
__global__ __launch_bounds__(256) void init_p(
    const float* __restrict__ x, const float* __restrict__ wm,
    const float* __restrict__ bl, float* __restrict__ pT)
{
    __shared__ __align__(16) float  xs[128][68];
    __shared__ __align__(16) float2 wsp[16][64];
    __shared__ float bls[32];

    int r = blockIdx.x, b = blockIdx.y;
    int tid = threadIdx.x;

    if (tid < 32) bls[tid] = bl[tid];
    for (int i = tid; i < 16 * 64; i += 256) {
        int dp = i >> 6, f = i & 63;
        wsp[dp][f] = make_float2(wm[(2 * dp) * 64 + f], wm[(2 * dp + 1) * 64 + f]);
    }

    bool border_r = (r == 0 || r == 127);
    if (!border_r) {
        for (int i = tid; i < 128 * 64; i += 256) {
            int c = i >> 6, f = i & 63;
            float val = 0.0f;
            if (c >= 1 && c <= 126)
                val = x[((b * 126 + (r - 1)) * 126 + (c - 1)) * 64 + f];
            xs[c][f] = val;
        }
    }
    __syncthreads();

    if (border_r) {
        for (int i = tid; i < 32 * 128; i += 256) {
            int d = i >> 7, c = i & 127;
            pT[((b * 32 + d) * 128 + r) * 128 + c] = bls[d];
        }
        return;
    }

    int lane = tid & 31;
    int wz   = tid >> 5;
    int dp0  = 2 * wz;

    ull acc[2][4];
#pragma unroll
    for (int dp = 0; dp < 2; dp++)
#pragma unroll
        for (int j = 0; j < 4; j++) acc[dp][j] = 0ULL;

#pragma unroll 4
    for (int fc = 0; fc < 16; fc++) {
        float4 xv[4];
#pragma unroll
        for (int j = 0; j < 4; j++)
            xv[j] = reinterpret_cast<const float4*>(&xs[lane + 32 * j][0])[fc];

        ulonglong2 wA0 = *reinterpret_cast<const ulonglong2*>(&wsp[dp0][4 * fc]);
        ulonglong2 wB0 = *reinterpret_cast<const ulonglong2*>(&wsp[dp0][4 * fc + 2]);
        ulonglong2 wA1 = *reinterpret_cast<const ulonglong2*>(&wsp[dp0 + 1][4 * fc]);
        ulonglong2 wB1 = *reinterpret_cast<const ulonglong2*>(&wsp[dp0 + 1][4 * fc + 2]);
        ull w0[4] = { wA0.x, wA0.y, wB0.x, wB0.y };
        ull w1[4] = { wA1.x, wA1.y, wB1.x, wB1.y };

#pragma unroll
        for (int j = 0; j < 4; j++) {
            const float* xvf = reinterpret_cast<const float*>(&xv[j]);
#pragma unroll
            for (int k = 0; k < 4; k++) {
                ull xx = pk2(xvf[k], xvf[k]);
                fma2(acc[0][j], xx, w0[k]);
                fma2(acc[1][j], xx, w1[k]);
            }
        }
    }

#pragma unroll
    for (int dp = 0; dp < 2; dp++) {
        int d = 4 * wz + 2 * dp;
        float bl0 = bls[d], bl1 = bls[d + 1];
#pragma unroll
        for (int j = 0; j < 4; j++) {
            int c = lane + 32 * j;
            pT[((b * 32 + d)     * 128 + r) * 128 + c] = lo32(acc[dp][j]) + bl0;
            pT[((b * 32 + d + 1) * 128 + r) * 128 + c] = hi32(acc[dp][j]) + bl1;
        }
    }
}

// ---------------------------------------------------------------------------
// Vectorized transpose: [b][r][c][d] -> [(b*32+d)][r][c]. Block per (r,b,field).
// LDG.128 coalesced over (c,d4); smem tile; STG.128 coalesced over c.
// ---------------------------------------------------------------------------
__global__ __launch_bounds__(256) void transpose_uv(
    const float* __restrict__ u0, const float* __restrict__ v0,
    float* __restrict__ uT, float* __restrict__ vT)
{
    __shared__ float tile[32][129];   // [d][c]
    int r = blockIdx.x, b = blockIdx.y;
    const float4* src = (const float4*)((blockIdx.z == 0) ? u0 : v0);
    float4*       dst = (float4*)((blockIdx.z == 0) ? uT : vT);
    int tid = threadIdx.x;

    size_t inbase = ((size_t)(b * 128 + r)) * 128 * 8;   // float4 units
#pragma unroll
    for (int j = 0; j < 4; j++) {
        int c  = (tid >> 3) + 32 * j;
        int d4 = tid & 7;
        float4 v = src[inbase + c * 8 + d4];
        tile[d4 * 4 + 0][c] = v.x;
        tile[d4 * 4 + 1][c] = v.y;
        tile[d4 * 4 + 2][c] = v.z;
        tile[d4 * 4 + 3][c] = v.w;
    }
    __syncthreads();

#pragma unroll
    for (int j = 0; j < 4; j++) {
        int d  = (tid >> 5) + 8 * j;
        int c4 = tid & 31;
        float4 o = make_float4(tile[d][4 * c4 + 0], tile[d][4 * c4 + 1],
                               tile[d][4 * c4 + 2], tile[d][4 * c4 + 3]);
        dst[((size_t)(b * 32 + d) * 128 + r) * 32 + c4] = o;
    }
}

// ---------------------------------------------------------------------------
// Fused sim: 128 CTAs x 512 thr; CTA = planes (2k, 2k+1). 16 warps; warp w
// owns rows 8w..8w+7 of BOTH planes; lane owns cols 4l..4l+3.
// P in registers (64 regs); C in smem (warp-private rows, no barrier);
// u,v in global (double-buffered, coalesced). One barrier per sweep.
// smem: C 2x128x32 f4 (128 KB) + halo 2buf x 2pl x 16w x 2 x 32 f4 (64 KB).
// ---------------------------------------------------------------------------
extern __shared__ float4 dsm[];
#define SMC(pl, r, l)          dsm[(pl) * 4096 + (r) * 32 + (l)]
#define HLX(buf, pl, w, tb, l) dsm[8192 + (((((buf) * 2 + (pl)) * 16 + (w)) * 2 + (tb)) * 32) + (l)]

__device__ __forceinline__ float4 jrow(float4 cur, float4 N, float4 S, float4 C,
                                       int laneW, int laneE) {
    float w0 = __shfl_sync(0xffffffffu, cur.w, laneW);
    float e3 = __shfl_sync(0xffffffffu, cur.x, laneE);
    float4 o;
    o.x = __fmaf_rn(cur.y, F_A, __fmaf_rn(w0,    F_A, __fmaf_rn(N.x, F_B, __fmaf_rn(S.x, F_B, C.x))));
    o.y = __fmaf_rn(cur.z, F_A, __fmaf_rn(cur.x, F_A, __fmaf_rn(N.y, F_B, __fmaf_rn(S.y, F_B, C.y))));
    o.z = __fmaf_rn(cur.w, F_A, __fmaf_rn(cur.y, F_A, __fmaf_rn(N.z, F_B, __fmaf_rn(S.z, F_B, C.z))));
    o.w = __fmaf_rn(e3,    F_A, __fmaf_rn(cur.z, F_A, __fmaf_rn(N.w, F_B, __fmaf_rn(S.w, F_B, C.w))));
    return o;
}

__device__ __forceinline__ float4 jrowH(float4 cur, float4 R, float4 H, float4 C,
                                        int laneW, int laneE) {
    float w0 = __shfl_sync(0xffffffffu, cur.w, laneW);
    float e3 = __shfl_sync(0xffffffffu, cur.x, laneE);
    float4 o;
    o.x = __fmaf_rn(H.x, F_B, __fmaf_rn(cur.y, F_A, __fmaf_rn(w0,    F_A, __fmaf_rn(R.x, F_B, C.x))));
    o.y = __fmaf_rn(H.y, F_B, __fmaf_rn(cur.z, F_A, __fmaf_rn(cur.x, F_A, __fmaf_rn(R.y, F_B, C.y))));
    o.z = __fmaf_rn(H.z, F_B, __fmaf_rn(cur.w, F_A, __fmaf_rn(cur.y, F_A, __fmaf_rn(R.z, F_B, C.z))));
    o.w = __fmaf_rn(H.w, F_B, __fmaf_rn(e3,    F_A, __fmaf_rn(cur.z, F_A, __fmaf_rn(R.w, F_B, C.w))));
    return o;
}

// build_b for one plane: coalesced global u,v reads -> C rows in smem
__device__ __forceinline__ void build_b_plane(
    const float4* __restrict__ uc, const float4* __restrict__ vc,
    int pl, int r0, int lane, int laneW, int laneE)
{
#pragma unroll
    for (int i = 0; i < 8; i++) {
        int r = r0 + i;
        if (r < 1 || r > 126) continue;
        float4 uo = uc[r * 32 + lane], un = uc[(r - 1) * 32 + lane], us = uc[(r + 1) * 32 + lane];
        float4 vo = vc[r * 32 + lane], vn = vc[(r - 1) * 32 + lane], vs = vc[(r + 1) * 32 + lane];
        float uw0 = __shfl_sync(0xffffffffu, uo.w, laneW);
        float ue3 = __shfl_sync(0xffffffffu, uo.x, laneE);
        float vw0 = __shfl_sync(0xffffffffu, vo.w, laneW);
        float ve3 = __shfl_sync(0xffffffffu, vo.x, laneE);
        float4 cv;
#define BQ(q, UW, UE, VW, VE) { \
        float dudx = (UE - UW) * F_I2DX; \
        float dvdy = (vs.q - vn.q) * F_I2DY; \
        float dudy = (us.q - un.q) * F_I2DY; \
        float dvdx = (VE - VW) * F_I2DX; \
        float bv = (dudx + dvdy) * F_IDT - dudx * dudx \
                 - 2.0f * dudy * dvdx - dvdy * dvdy; \
        cv.q = -F_CB * bv; }
        BQ(x, uw0,  uo.y, vw0,  vo.y)
        BQ(y, uo.x, uo.z, vo.x, vo.z)
        BQ(z, uo.y, uo.w, vo.y, vo.w)
        BQ(w, uo.z, ue3,  vo.z, ve3)
#undef BQ
        SMC(pl, r, lane) = cv;
    }
}

// velocity for one plane: reads OLD u,v (global) + final p (regs/halo),
// writes NEW u,v to a different global buffer (no in-place hazard).
__device__ __forceinline__ void velocity_plane(
    float4 (&P)[8],
    const float4* __restrict__ uc, const float4* __restrict__ vc,
    float4* __restrict__ uo_, float4* __restrict__ vo_,
    int pl, int r0, int lane, int laneW, int laneE,
    bool topw, bool botw, int wid)
{
    float4 z4 = make_float4(0.f, 0.f, 0.f, 0.f);
    float4 phN = topw ? z4 : HLX(0, pl, wid - 1, 1, lane);
    float4 phS = botw ? z4 : HLX(0, pl, wid + 1, 0, lane);

#pragma unroll
    for (int i = 0; i < 8; i++) {
        int r = r0 + i;
        if (r < 1 || r > 126) {
            uo_[r * 32 + lane] = z4;
            vo_[r * 32 + lane] = z4;
            continue;
        }
        float4 uo = uc[r * 32 + lane], un = uc[(r - 1) * 32 + lane], us = uc[(r + 1) * 32 + lane];
        float4 vo = vc[r * 32 + lane], vn = vc[(r - 1) * 32 + lane], vs = vc[(r + 1) * 32 + lane];
        float4 pN = (i > 0) ? P[i - 1] : phN;
        float4 pS = (i < 7) ? P[i + 1] : phS;
        float4 po = P[i];
        float uw0 = __shfl_sync(0xffffffffu, uo.w, laneW);
        float ue3 = __shfl_sync(0xffffffffu, uo.x, laneE);
        float vw0 = __shfl_sync(0xffffffffu, vo.w, laneW);
        float ve3 = __shfl_sync(0xffffffffu, vo.x, laneE);
        float pw0 = __shfl_sync(0xffffffffu, po.w, laneW);
        float pe3 = __shfl_sync(0xffffffffu, po.x, laneE);
        float4 ru, rv;
#define VQ(q, UW, UE, VW, VE, PW, PE) { \
        float ucv = uo.q, vcv = vo.q; \
        ru.q = ucv - ucv * F_DTDX * (ucv - UW) - vcv * F_DTDY * (ucv - un.q) \
             - F_PGX * (PE - PW) \
             + F_NUX * (UE - 2.0f * ucv + UW) + F_NUY * (us.q - 2.0f * ucv + un.q) \
             + F_FDT; \
        rv.q = vcv - ucv * F_DTDX * (vcv - VW) - vcv * F_DTDY * (vcv - vn.q) \
             - F_PGY * (pS.q - pN.q) \
             + F_NUX * (VE - 2.0f * vcv + VW) + F_NUY * (vs.q - 2.0f * vcv + vn.q); }
        VQ(x, uw0,  uo.y, vw0,  vo.y, pw0,  po.y)
        VQ(y, uo.x, uo.z, vo.x, vo.z, po.x, po.z)
        VQ(z, uo.y, uo.w, vo.y, vo.w, po.y, po.w)
        VQ(w, uo.z, ue3,  vo.z, ve3,  po.z, pe3)
#undef VQ
        uo_[r * 32 + lane] = ru;
        vo_[r * 32 + lane] = rv;
    }
}

__global__ __launch_bounds__(512) void fused_sim(
    const float4* __restrict__ pT,
    const float4* __restrict__ uT, const float4* __restrict__ vT,
    float4* __restrict__ uA, float4* __restrict__ vA,
    float4* __restrict__ uB, float4* __restrict__ vB,
    float* __restrict__ out)
{
    int pr   = blockIdx.x;               // plane pair
    int bd0  = pr * 2, bd1 = bd0 + 1;
    int tid  = threadIdx.x;
    int lane = tid & 31;
    int wid  = tid >> 5;
    int r0   = wid << 3;
    int laneW = (lane + 31) & 31;
    int laneE = (lane + 1) & 31;
    const bool topw = (wid == 0);
    const bool botw = (wid == 15);

    float4 P0[8], P1[8];
    {
        const float4* p0 = pT + (size_t)bd0 * NPF4;
        const float4* p1 = pT + (size_t)bd1 * NPF4;
#pragma unroll
        for (int i = 0; i < 8; i++) {
            P0[i] = p0[(r0 + i) * 32 + lane];
            P1[i] = p1[(r0 + i) * 32 + lane];
        }
    }

    const float4* uc0 = uT + (size_t)bd0 * NPF4;
    const float4* vc0 = vT + (size_t)bd0 * NPF4;
    const float4* uc1 = uT + (size_t)bd1 * NPF4;
    const float4* vc1 = vT + (size_t)bd1 * NPF4;

    for (int it = 0; it < 3; it++) {
        // ---- build_b -> C smem (warp-private rows; no barrier needed) -----
        build_b_plane(uc0, vc0, 0, r0, lane, laneW, laneE);
        build_b_plane(uc1, vc1, 1, r0, lane, laneW, laneE);

        // ---- initial halo publish (time-t) into buf 0 ---------------------
        HLX(0, 0, wid, 0, lane) = P0[0];
        HLX(0, 0, wid, 1, lane) = P0[7];
        HLX(0, 1, wid, 0, lane) = P1[0];
        HLX(0, 1, wid, 1, lane) = P1[7];

        // ---- 20 Jacobi sweeps, both planes per barrier --------------------
#pragma unroll 1
        for (int s = 0; s < 20; s++) {
            int rb = s & 1, wb = rb ^ 1;
            float4 oP1_0 = P0[1], oP6_0 = P0[6];
            {
                float4 oldN = P0[0];
#pragma unroll
                for (int i = 1; i <= 6; i++) {
                    float4 cur = P0[i];
                    P0[i] = jrow(cur, oldN, P0[i + 1], SMC(0, r0 + i, lane), laneW, laneE);
                    oldN = cur;
                }
            }
            float4 oP1_1 = P1[1], oP6_1 = P1[6];
            {
                float4 oldN = P1[0];
#pragma unroll
                for (int i = 1; i <= 6; i++) {
                    float4 cur = P1[i];
                    P1[i] = jrow(cur, oldN, P1[i + 1], SMC(1, r0 + i, lane), laneW, laneE);
                    oldN = cur;
                }
            }
            __syncthreads();
            if (!botw) {
                float4 hS0 = HLX(rb, 0, wid + 1, 0, lane);
                float4 hS1 = HLX(rb, 1, wid + 1, 0, lane);
                P0[7] = jrowH(P0[7], oP6_0, hS0, SMC(0, r0 + 7, lane), laneW, laneE);
                P1[7] = jrowH(P1[7], oP6_1, hS1, SMC(1, r0 + 7, lane), laneW, laneE);
            } else {
                P0[7] = P0[6];
                P1[7] = P1[6];
            }
            if (!topw) {
                float4 hN0 = HLX(rb, 0, wid - 1, 1, lane);
                float4 hN1 = HLX(rb, 1, wid - 1, 1, lane);
                P0[0] = jrowH(P0[0], oP1_0, hN0, SMC(0, r0, lane), laneW, laneE);
                P1[0] = jrowH(P1[0], oP1_1, hN1, SMC(1, r0, lane), laneW, laneE);
            } else {
                P0[0] = P0[1];
                P1[0] = P1[1];
            }
            HLX(wb, 0, wid, 0, lane) = P0[0];
            HLX(wb, 0, wid, 1, lane) = P0[7];
            HLX(wb, 1, wid, 0, lane) = P1[0];
            HLX(wb, 1, wid, 1, lane) = P1[7];
        }
        // last publish went to buf 0 (s=19: wb=0)

        // ---- velocity (it 0,1; it 2's result is dead) ---------------------
        if (it < 2) {
            __syncthreads();   // final halo publish visible
            float4* unG0 = ((it == 0) ? uA : uB) + (size_t)bd0 * NPF4;
            float4* vnG0 = ((it == 0) ? vA : vB) + (size_t)bd0 * NPF4;
            float4* unG1 = ((it == 0) ? uA : uB) + (size_t)bd1 * NPF4;
            float4* vnG1 = ((it == 0) ? vA : vB) + (size_t)bd1 * NPF4;
            velocity_plane(P0, uc0, vc0, unG0, vnG0, 0, r0, lane, laneW, laneE, topw, botw, wid);
            velocity_plane(P1, uc1, vc1, unG1, vnG1, 1, r0, lane, laneW, laneE, topw, botw, wid);
            __syncthreads();   // new u,v visible CTA-wide for next build_b
            uc0 = unG0; vc0 = vnG0;
            uc1 = unG1; vc1 = vnG1;
        }
    }

    // ---- output: out[(b*128 + c)*32 + d] = p[row 127][c], both planes -----
    if (botw) {
        int b = bd0 >> 5, d0 = bd0 & 31, d1 = bd1 & 31;
        int cb = lane << 2;
#pragma unroll
        for (int k = 0; k < 4; k++) {
            float v0k = (k == 0) ? P0[7].x : (k == 1) ? P0[7].y : (k == 2) ? P0[7].z : P0[7].w;
            float v1k = (k == 0) ? P1[7].x : (k == 1) ? P1[7].y : (k == 2) ? P1[7].z : P1[7].w;
            out[((b << 7) + cb + k) * 32 + d0] = v0k;
            out[((b << 7) + cb + k) * 32 + d1] = v1k;
        }
    }
}

// ---------------------------------------------------------------------------
// Host driver
// ---------------------------------------------------------------------------
extern "C" void kernel_launch(void* const* d_in, const int* in_sizes, int n_in,
                              void* d_out, int out_size)
{
    const float* x    = (const float*)d_in[0];
    const float* u0   = (const float*)d_in[1];
    const float* v0   = (const float*)d_in[2];
    const float* wm   = (const float*)d_in[3];
    const float* blin = (const float*)d_in[4];

    float *pT, *uT, *vT, *uA, *vA, *uB, *vB;
    cudaGetSymbolAddress((void**)&pT, g_pT);
    cudaGetSymbolAddress((void**)&uT, g_uT);
    cudaGetSymbolAddress((void**)&vT, g_vT);
    cudaGetSymbolAddress((void**)&uA, g_uA);
    cudaGetSymbolAddress((void**)&vA, g_vA);
    cudaGetSymbolAddress((void**)&uB, g_uB);
    cudaGetSymbolAddress((void**)&vB, g_vB);

    const int SMEM = 12288 * (int)sizeof(float4);   // 192 KB
    cudaFuncSetAttribute(fused_sim, cudaFuncAttributeMaxDynamicSharedMemorySize, SMEM);

    transpose_uv<<<dim3(128, 8, 2), 256>>>(u0, v0, uT, vT);
    init_p<<<dim3(128, 8), 256>>>(x, wm, blin, pT);

    fused_sim<<<128, 512, SMEM>>>(
        (const float4*)pT, (const float4*)uT, (const float4*)vT,
        (float4*)uA, (float4*)vA, (float4*)uB, (float4*)vB,
        (float*)d_out);
}